// round 7
// baseline (speedup 1.0000x reference)
#include <cuda_runtime.h>
#include <cuda_bf16.h>
#include <math.h>

// Problem constants
#define C 144
#define W 77
#define KW 10
#define FC 64
#define CONV_OUT 68                   // W - KW + 1
#define FC_N (C*FC)                   // 9216
#define CONCAT_N (FC_N + CONV_OUT)    // 9284
#define H2 128

#define NB_FC (C*2)                   // 288 blocks: (channel, half of 32 outputs)
#define NB_CV 4                       // 4 conv blocks x 17 outputs
#define CV_PER_BLK 17
#define GRID (NB_FC + NB_CV)          // 292

// Scratch (no allocations allowed)
__device__ float g_part[GRID * H2];   // per-block partial contributions to h_pre
__device__ int g_done;

__device__ __forceinline__ float warp_reduce(float v) {
    #pragma unroll
    for (int o = 16; o > 0; o >>= 1) v += __shfl_xor_sync(0xffffffffu, v, o);
    return v;
}

__global__ __launch_bounds__(256) void fused_onepass(
    const float* __restrict__ x,       // [C, W]
    const float* __restrict__ fc_w,    // [C*FC, W]
    const float* __restrict__ fc_b,    // [C*FC]
    const float* __restrict__ conv_w,  // [C*KW] = 1440
    const float* __restrict__ conv_b,  // [1]
    const float* __restrict__ w2,      // [H2, CONCAT_N]
    const float* __restrict__ b2,      // [H2]
    const float* __restrict__ w3,      // [H2]
    const float* __restrict__ b3,      // [1]
    float* __restrict__ out)           // [1]
{
    const int b = blockIdx.x;
    const int tid = threadIdx.x;
    const int warp = tid >> 5, lane = tid & 31;

    __shared__ float xs[W];
    __shared__ __align__(16) float fcs[CONV_OUT];  // 32 fc outs, or up to 17 conv outs
    __shared__ float hv[H2];
    __shared__ int is_last;

    if (b < NB_FC) {
        // ---- FC slice: channel c, outputs d in [half*32, half*32+32) ----
        const int c = b >> 1, half = b & 1;
        if (tid < W) xs[tid] = x[c * W + tid];
        __syncthreads();

        #pragma unroll
        for (int i = 0; i < 4; i++) {
            const int dl = warp * 4 + i;                       // 0..31 local
            const int o  = c * FC + half * 32 + dl;            // global fc row
            const float* __restrict__ wr = fc_w + (size_t)o * W;
            float s = wr[lane] * xs[lane] + wr[lane + 32] * xs[lane + 32];
            if (lane < 13) s += wr[lane + 64] * xs[lane + 64];
            s = warp_reduce(s);
            if (lane == 0) fcs[dl] = s + fc_b[o];
        }
        __syncthreads();

        // ---- Consume against w2 column slice: 128 threads, one j each ----
        if (tid < H2) {
            const float4* __restrict__ wr4 =
                reinterpret_cast<const float4*>(w2 + (size_t)tid * CONCAT_N + c * FC + half * 32);
            const float4* __restrict__ f4 = reinterpret_cast<const float4*>(fcs);
            float a0 = 0.f, a1 = 0.f, a2 = 0.f, a3 = 0.f;
            #pragma unroll
            for (int q = 0; q < 8; q += 4) {
                float4 w0 = wr4[q],   c0 = f4[q];
                float4 w1 = wr4[q+1], c1 = f4[q+1];
                float4 w2v = wr4[q+2], c2 = f4[q+2];
                float4 w3v = wr4[q+3], c3 = f4[q+3];
                a0 += w0.x*c0.x + w0.y*c0.y + w0.z*c0.z + w0.w*c0.w;
                a1 += w1.x*c1.x + w1.y*c1.y + w1.z*c1.z + w1.w*c1.w;
                a2 += w2v.x*c2.x + w2v.y*c2.y + w2v.z*c2.z + w2v.w*c2.w;
                a3 += w3v.x*c3.x + w3v.y*c3.y + w3v.z*c3.z + w3v.w*c3.w;
            }
            g_part[b * H2 + tid] = (a0 + a1) + (a2 + a3);
        }
    } else {
        // ---- Conv slice: outputs o in [cb*17, cb*17+17) ----
        const int cb = b - NB_FC;
        const int obase = cb * CV_PER_BLK;
        for (int oo = warp; oo < CV_PER_BLK; oo += 8) {
            const int o = obase + oo;
            float s = 0.f;
            int c = lane / KW, k = lane - (lane / KW) * KW;
            #pragma unroll
            for (int it = 0; it < 45; it++) {          // i = lane + 32*it over 1440
                s += conv_w[c * KW + k] * x[c * W + o + k];
                k += 2; c += 3;
                if (k >= KW) { k -= KW; c += 1; }
            }
            s = warp_reduce(s);
            if (lane == 0) fcs[oo] = s + conv_b[0];
        }
        __syncthreads();

        if (tid < H2) {
            const float* __restrict__ wr = w2 + (size_t)tid * CONCAT_N + FC_N + obase;
            float a0 = 0.f, a1 = 0.f;
            #pragma unroll
            for (int q = 0; q < 16; q += 2) {
                a0 += wr[q] * fcs[q];
                a1 += wr[q + 1] * fcs[q + 1];
            }
            a0 += wr[16] * fcs[16];
            g_part[b * H2 + tid] = a0 + a1;
        }
    }

    // ---- Completion detection ----
    __syncthreads();
    if (tid == 0) {
        __threadfence();
        const int n = atomicAdd(&g_done, 1);
        is_last = (n == GRID - 1) ? 1 : 0;
    }
    __syncthreads();

    // ---- Tail: reduce 292 partial rows, bias+relu, head (last block only) ----
    if (is_last) {
        __threadfence();
        if (tid < H2) {
            float s0 = 0.f, s1 = 0.f, s2 = 0.f, s3 = 0.f;
            #pragma unroll 4
            for (int r = 0; r < GRID; r += 4) {        // 292 divisible by 4
                s0 += g_part[(r    ) * H2 + tid];
                s1 += g_part[(r + 1) * H2 + tid];
                s2 += g_part[(r + 2) * H2 + tid];
                s3 += g_part[(r + 3) * H2 + tid];
            }
            hv[tid] = fmaxf((s0 + s1) + (s2 + s3) + b2[tid], 0.f);
        }
        __syncthreads();
        if (warp == 0) {
            float acc = 0.f;
            #pragma unroll
            for (int q = 0; q < 4; q++) {
                const int r = lane + q * 32;
                acc += w3[r] * hv[r];
            }
            acc = warp_reduce(acc);
            if (lane == 0) {
                acc = fmaxf(acc + b3[0], 0.f);
                out[0] = 1.f / (1.f + expf(-acc));
                g_done = 0;                            // reset for next replay
            }
        }
    }
}

extern "C" void kernel_launch(void* const* d_in, const int* in_sizes, int n_in,
                              void* d_out, int out_size) {
    const float* x      = (const float*)d_in[0];
    const float* fc_w   = (const float*)d_in[1];
    const float* fc_b   = (const float*)d_in[2];
    const float* conv_w = (const float*)d_in[3];
    const float* conv_b = (const float*)d_in[4];
    const float* w2     = (const float*)d_in[5];
    const float* b2     = (const float*)d_in[6];
    const float* w3     = (const float*)d_in[7];
    const float* b3     = (const float*)d_in[8];
    float* out = (float*)d_out;

    fused_onepass<<<GRID, 256>>>(x, fc_w, fc_b, conv_w, conv_b, w2, b2, w3, b3, out);
}

// round 10
// speedup vs baseline: 1.7589x; 1.7589x over previous
#include <cuda_runtime.h>
#include <cuda_bf16.h>
#include <math.h>

// Problem constants
#define C 144
#define W 77
#define KW 10
#define FC 64
#define CONV_OUT 68                  // W - KW + 1
#define FC_N (C*FC)                  // 9216
#define CONCAT_N (FC_N + CONV_OUT)   // 9284
#define CONCAT_V4 (CONCAT_N/4)       // 2321
#define H2 128
#define SPLIT 4
#define CHUNK 581                    // ceil(2321/4)

#define K1_GRID (1152 + CONV_OUT)    // 1220
#define K2_GRID (H2 * SPLIT)         // 512

// Scratch (no allocations allowed)
__device__ __align__(16) float g_concat[CONCAT_N];
__device__ float g_part[H2 * SPLIT];
__device__ int g_done;

__device__ __forceinline__ float warp_reduce(float v) {
    #pragma unroll
    for (int o = 16; o > 0; o >>= 1) v += __shfl_xor_sync(0xffffffffu, v, o);
    return v;
}

// K1: one warp per FC output (blocks 0..1151), one block per conv output (1152..1219).
__global__ __launch_bounds__(256) void k1_fc_conv(
    const float* __restrict__ x,       // [C, W]
    const float* __restrict__ fc_w,    // [C*FC, W]
    const float* __restrict__ fc_b,    // [C*FC]
    const float* __restrict__ conv_w,  // [C*KW]
    const float* __restrict__ conv_b)  // [1]
{
    // PDL: signal dependent launch as early as possible (all blocks must pass this).
    asm volatile("griddepcontrol.launch_dependents;" ::: "memory");

    const int b = blockIdx.x;
    const int tid = threadIdx.x;
    const int warp = tid >> 5, lane = tid & 31;

    if (b < 1152) {
        const int w = b * 8 + warp;            // global output index 0..9215
        const int c = w >> 6;                  // channel
        const float* __restrict__ wrow = fc_w + (size_t)w * W;
        const float* __restrict__ xr   = x + c * W;
        float s = wrow[lane] * xr[lane] + wrow[lane + 32] * xr[lane + 32];
        if (lane < 13) s += wrow[lane + 64] * xr[lane + 64];
        s = warp_reduce(s);
        if (lane == 0) g_concat[w] = s + fc_b[w];
    } else {
        const int o = b - 1152;                // conv output 0..67
        float s = 0.f;
        for (int i = tid; i < C * KW; i += 256) {
            const int c = i / KW, k = i - c * KW;
            s += conv_w[i] * x[c * W + o + k];
        }
        s = warp_reduce(s);
        __shared__ float red[8];
        if (lane == 0) red[warp] = s;
        __syncthreads();
        if (tid == 0) {
            float t = red[0];
            #pragma unroll
            for (int q = 1; q < 8; q++) t += red[q];
            g_concat[FC_N + o] = t + conv_b[0];
        }
    }
}

// K2: split-K GEMV with PDL register-prefetch of w2 before the grid dependency wait.
__global__ __launch_bounds__(256) void k2_head(
    const float* __restrict__ w2,   // [H2, CONCAT_N]
    const float* __restrict__ b2,   // [H2]
    const float* __restrict__ w3,   // [H2]
    const float* __restrict__ b3,   // [1]
    float* __restrict__ out)        // [1]
{
    const int blk = blockIdx.x;
    const int j  = blk >> 2;        // row 0..127
    const int sp = blk & 3;         // chunk 0..3
    const int tid = threadIdx.x;
    const int warp = tid >> 5, lane = tid & 31;

    const int start = sp * CHUNK;
    const int end = (start + CHUNK < CONCAT_V4) ? start + CHUNK : CONCAT_V4;
    const int i0 = start + tid;
    const bool v2 = (i0 + 512 < end);   // i0, i0+256 always valid (end-start >= 578)

    const float4* __restrict__ wrow = reinterpret_cast<const float4*>(w2 + (size_t)j * CONCAT_N);

    // ---- Pre-sync: prefetch w2 into registers (independent of k1) ----
    const float4 w0 = wrow[i0];
    const float4 w1 = wrow[i0 + 256];
    float4 wv2 = make_float4(0.f, 0.f, 0.f, 0.f);
    if (v2) wv2 = wrow[i0 + 512];

    // ---- Wait for k1 completion (memory visibility of g_concat) ----
    asm volatile("griddepcontrol.wait;" ::: "memory");

    const float4* __restrict__ cc = reinterpret_cast<const float4*>(g_concat);
    const float4 c0 = cc[i0];
    const float4 c1 = cc[i0 + 256];
    float s = w0.x*c0.x + w0.y*c0.y + w0.z*c0.z + w0.w*c0.w
            + w1.x*c1.x + w1.y*c1.y + w1.z*c1.z + w1.w*c1.w;
    if (v2) {
        const float4 c2 = cc[i0 + 512];
        s += wv2.x*c2.x + wv2.y*c2.y + wv2.z*c2.z + wv2.w*c2.w;
    }
    s = warp_reduce(s);

    __shared__ float red[8];
    __shared__ int is_last;
    if (lane == 0) red[warp] = s;
    __syncthreads();

    if (tid == 0) {
        float t = red[0];
        #pragma unroll
        for (int q = 1; q < 8; q++) t += red[q];
        g_part[j * SPLIT + sp] = t;
        __threadfence();
        const int n = atomicAdd(&g_done, 1);
        is_last = (n == K2_GRID - 1) ? 1 : 0;
    }
    __syncthreads();

    if (is_last && warp == 0) {
        __threadfence();
        float acc = 0.f;
        #pragma unroll
        for (int q = 0; q < 4; q++) {
            const int r = lane + q * 32;
            const float v = g_part[r * SPLIT + 0] + g_part[r * SPLIT + 1]
                          + g_part[r * SPLIT + 2] + g_part[r * SPLIT + 3];
            const float h = fmaxf(v + b2[r], 0.f);
            acc += w3[r] * h;
        }
        acc = warp_reduce(acc);
        if (lane == 0) {
            acc = fmaxf(acc + b3[0], 0.f);
            out[0] = 1.f / (1.f + expf(-acc));
            g_done = 0;                // reset for next replay
        }
    }
}

extern "C" void kernel_launch(void* const* d_in, const int* in_sizes, int n_in,
                              void* d_out, int out_size) {
    const float* x      = (const float*)d_in[0];
    const float* fc_w   = (const float*)d_in[1];
    const float* fc_b   = (const float*)d_in[2];
    const float* conv_w = (const float*)d_in[3];
    const float* conv_b = (const float*)d_in[4];
    const float* w2     = (const float*)d_in[5];
    const float* b2     = (const float*)d_in[6];
    const float* w3     = (const float*)d_in[7];
    const float* b3     = (const float*)d_in[8];
    float* out = (float*)d_out;

    k1_fc_conv<<<K1_GRID, 256>>>(x, fc_w, fc_b, conv_w, conv_b);

    // k2 with programmatic dependent launch: overlaps its w2 prefetch with k1's tail.
    cudaLaunchConfig_t cfg = {};
    cfg.gridDim = dim3(K2_GRID);
    cfg.blockDim = dim3(256);
    cfg.dynamicSmemBytes = 0;
    cfg.stream = 0;
    cudaLaunchAttribute attr[1];
    attr[0].id = cudaLaunchAttributeProgrammaticStreamSerialization;
    attr[0].val.programmaticStreamSerializationAllowed = 1;
    cfg.attrs = attr;
    cfg.numAttrs = 1;
    cudaLaunchKernelEx(&cfg, k2_head, w2, b2, w3, b3, out);
}